// round 11
// baseline (speedup 1.0000x reference)
#include <cuda_runtime.h>

// ConvBertLightConv: dynamic depthwise conv, kernel=9, head=64.
// inputs:  [B=8, S=4096, D=768] fp32, filters: [B,S,108] fp32, out: [B,S,768].
//
// R10 (from R9): trade L1 bandwidth (abundant) for registers (the occupancy
// limiter). SREG 4->2, TILE_S 32->16: rin[10]=40 regs -> ~58 total, so
// launch_bounds(128,8) doubles warps/SM from 24 to 32 (occ 33%->50%).
// More independently-phased load bursts per SM -> higher HBM duty cycle.
// Still: one barrier, direct LDG inputs, warp-0 softmax, streaming stores.

#define S_LEN   4096
#define D_DIM   768
#define H_NUM   12
#define HD      64
#define KS      9
#define TILE_S  16
#define SREG    2
#define NTHREADS 128                 // 8 position-groups x 16 f4-columns
#define NROWS   (SREG + KS - 1)      // 10
#define ROW_F4  (D_DIM / 4)          // 192
#define FP      12                   // padded filter row stride (floats)

__device__ __forceinline__ void stcs128(float4* p, float4 v) {
    asm volatile("st.global.cs.v4.f32 [%0], {%1,%2,%3,%4};\n"
                 :: "l"(p), "f"(v.x), "f"(v.y), "f"(v.z), "f"(v.w));
}

__global__ __launch_bounds__(NTHREADS, 8)
void lightconv_kernel(const float* __restrict__ inputs,
                      const float* __restrict__ filters,
                      float* __restrict__ out)
{
    __shared__ float w_s[TILE_S * FP];        // softmaxed taps, 768 B

    const int tid = threadIdx.x;
    const int s0  = blockIdx.x * TILE_S;
    const int h   = blockIdx.y;
    const int b   = blockIdx.z;

    const int c   = tid & 15;                 // float4 column 0..15
    const int sl0 = (tid >> 4) * SREG;        // local base position 0..14

    // ---- front-batched input loads: 10 rows into registers ----
    const float4* in_g =
        (const float4*)(inputs + (size_t)b * S_LEN * D_DIM + h * HD);
    const int gbase = s0 + sl0 - (KS / 2);

    float4 rin[NROWS];
    if (s0 >= (KS / 2) && s0 + TILE_S + (KS / 2) <= S_LEN) {
        #pragma unroll
        for (int j = 0; j < NROWS; j++)
            rin[j] = __ldg(&in_g[(size_t)(gbase + j) * ROW_F4 + c]);
    } else {
        #pragma unroll
        for (int j = 0; j < NROWS; j++) {
            const int g = gbase + j;
            rin[j] = make_float4(0.f, 0.f, 0.f, 0.f);
            if (g >= 0 && g < S_LEN)
                rin[j] = __ldg(&in_g[(size_t)g * ROW_F4 + c]);
        }
    }

    // ---- first 16 threads: load taps, softmax, publish (overlaps LDGs) ----
    if (tid < TILE_S) {
        const float* f =
            filters + (size_t)(b * S_LEN + s0 + tid) * (H_NUM * KS) + h * KS;
        float v[KS];
        float m = -1e30f;
        #pragma unroll
        for (int k = 0; k < KS; k++) {
            v[k] = __ldg(f + k);
            m = fmaxf(m, v[k]);
        }
        float sum = 0.f;
        #pragma unroll
        for (int k = 0; k < KS; k++) { v[k] = __expf(v[k] - m); sum += v[k]; }
        const float inv = 1.0f / sum;
        #pragma unroll
        for (int k = 0; k < KS; k++) w_s[tid * FP + k] = v[k] * inv;
    }
    __syncthreads();                          // the ONLY barrier

    // ---- FMA: row j feeds output i at tap k = j - i ----
    float4 acc[SREG];
    #pragma unroll
    for (int i = 0; i < SREG; i++) acc[i] = make_float4(0.f, 0.f, 0.f, 0.f);

    #pragma unroll
    for (int j = 0; j < NROWS; j++) {
        const float4 r = rin[j];
        #pragma unroll
        for (int i = 0; i < SREG; i++) {
            const int k = j - i;
            if (k >= 0 && k < KS) {
                const float w = w_s[(sl0 + i) * FP + k];
                acc[i].x = fmaf(w, r.x, acc[i].x);
                acc[i].y = fmaf(w, r.y, acc[i].y);
                acc[i].z = fmaf(w, r.z, acc[i].z);
                acc[i].w = fmaf(w, r.w, acc[i].w);
            }
        }
    }

    // ---- streaming stores (256B-contiguous per position) ----
    float4* out_g = (float4*)(out + (size_t)b * S_LEN * D_DIM + h * HD);
    #pragma unroll
    for (int i = 0; i < SREG; i++)
        stcs128(&out_g[(size_t)(s0 + sl0 + i) * ROW_F4 + c], acc[i]);
}

extern "C" void kernel_launch(void* const* d_in, const int* in_sizes, int n_in,
                              void* d_out, int out_size)
{
    const float* inputs  = (const float*)d_in[0];
    const float* filters = (const float*)d_in[1];
    if (n_in >= 2 && in_sizes[0] == 8 * 4096 * (H_NUM * KS)) {
        filters = (const float*)d_in[0];
        inputs  = (const float*)d_in[1];
    }
    float* out = (float*)d_out;

    dim3 grid(S_LEN / TILE_S, H_NUM, 8);   // 256 x 12 x 8 = 24576 CTAs
    lightconv_kernel<<<grid, NTHREADS>>>(inputs, filters, out);
}

// round 12
// speedup vs baseline: 1.0903x; 1.0903x over previous
#include <cuda_runtime.h>

// ConvBertLightConv: dynamic depthwise conv, kernel=9, head=64.
// inputs:  [B=8, S=4096, D=768] fp32, filters: [B,S,108] fp32, out: [B,S,768].
//
// R11 (from R9 best): rolling 6-row load window instead of a full 12-row
// register batch. Front-batch rows 0..5 (MLP_p1=6) before the one barrier;
// iteration j<6 of the FMA loop prefetches row j+6 into the consumed slot.
// Cuts rin regs 48->24 so launch_bounds(128,8) fits 64 regs: 32 warps/SM
// (occ ~50%) at R9's 3x L1 amplification (R10 showed 5x saturates L1).

#define S_LEN   4096
#define D_DIM   768
#define H_NUM   12
#define HD      64
#define KS      9
#define TILE_S  32
#define SREG    4
#define NTHREADS 128                 // 8 position-groups x 16 f4-columns
#define NROWS   (SREG + KS - 1)      // 12
#define WIN     6                    // rolling window size
#define ROW_F4  (D_DIM / 4)          // 192
#define FP      12                   // padded filter row stride (floats)

__device__ __forceinline__ void stcs128(float4* p, float4 v) {
    asm volatile("st.global.cs.v4.f32 [%0], {%1,%2,%3,%4};\n"
                 :: "l"(p), "f"(v.x), "f"(v.y), "f"(v.z), "f"(v.w));
}

template <bool EDGE>
__device__ __forceinline__ void conv_body(const float4* __restrict__ in_g,
                                          const float* __restrict__ w_s,
                                          float4* __restrict__ out_g,
                                          int s0, int sl0, int c)
{
    const int gbase = s0 + sl0 - (KS / 2);

    // front-batch the first WIN rows
    float4 rin[WIN];
    #pragma unroll
    for (int j = 0; j < WIN; j++) {
        if (EDGE) {
            const int g = gbase + j;
            rin[j] = make_float4(0.f, 0.f, 0.f, 0.f);
            if ((unsigned)g < (unsigned)S_LEN)
                rin[j] = __ldg(&in_g[(size_t)g * ROW_F4 + c]);
        } else {
            rin[j] = __ldg(&in_g[(size_t)(gbase + j) * ROW_F4 + c]);
        }
    }

    float4 acc[SREG];
    #pragma unroll
    for (int i = 0; i < SREG; i++) acc[i] = make_float4(0.f, 0.f, 0.f, 0.f);

    #pragma unroll
    for (int j = 0; j < NROWS; j++) {
        const float4 r = rin[j % WIN];
        // prefetch row j+WIN into the slot just freed
        if (j + WIN < NROWS) {
            if (EDGE) {
                const int g = gbase + j + WIN;
                rin[j % WIN] = make_float4(0.f, 0.f, 0.f, 0.f);
                if ((unsigned)g < (unsigned)S_LEN)
                    rin[j % WIN] = __ldg(&in_g[(size_t)g * ROW_F4 + c]);
            } else {
                rin[j % WIN] = __ldg(&in_g[(size_t)(gbase + j + WIN) * ROW_F4 + c]);
            }
        }
        #pragma unroll
        for (int i = 0; i < SREG; i++) {
            const int k = j - i;
            if (k >= 0 && k < KS) {
                const float w = w_s[(sl0 + i) * FP + k];
                acc[i].x = fmaf(w, r.x, acc[i].x);
                acc[i].y = fmaf(w, r.y, acc[i].y);
                acc[i].z = fmaf(w, r.z, acc[i].z);
                acc[i].w = fmaf(w, r.w, acc[i].w);
            }
        }
    }

    #pragma unroll
    for (int i = 0; i < SREG; i++)
        stcs128(&out_g[(size_t)(s0 + sl0 + i) * ROW_F4 + c], acc[i]);
}

__global__ __launch_bounds__(NTHREADS, 8)
void lightconv_kernel(const float* __restrict__ inputs,
                      const float* __restrict__ filters,
                      float* __restrict__ out)
{
    __shared__ float w_s[TILE_S * FP];        // softmaxed taps, 1536 B

    const int tid = threadIdx.x;
    const int s0  = blockIdx.x * TILE_S;
    const int h   = blockIdx.y;
    const int b   = blockIdx.z;

    const int c   = tid & 15;                 // float4 column 0..15
    const int sl0 = (tid >> 4) * SREG;        // local base position

    const float4* in_g =
        (const float4*)(inputs + (size_t)b * S_LEN * D_DIM + h * HD);
    float4* out_g = (float4*)(out + (size_t)b * S_LEN * D_DIM + h * HD);

    // ---- warp 0: load taps, softmax, publish (overlaps the load burst) ----
    if (tid < TILE_S) {
        const float* f =
            filters + (size_t)(b * S_LEN + s0 + tid) * (H_NUM * KS) + h * KS;
        float v[KS];
        float m = -1e30f;
        #pragma unroll
        for (int k = 0; k < KS; k++) {
            v[k] = __ldg(f + k);
            m = fmaxf(m, v[k]);
        }
        float sum = 0.f;
        #pragma unroll
        for (int k = 0; k < KS; k++) { v[k] = __expf(v[k] - m); sum += v[k]; }
        const float inv = 1.0f / sum;
        #pragma unroll
        for (int k = 0; k < KS; k++) w_s[tid * FP + k] = v[k] * inv;
    }
    __syncthreads();                          // the ONLY barrier

    if (s0 >= (KS / 2) && s0 + TILE_S + (KS / 2) <= S_LEN)
        conv_body<false>(in_g, w_s, out_g, s0, sl0, c);
    else
        conv_body<true >(in_g, w_s, out_g, s0, sl0, c);
}

extern "C" void kernel_launch(void* const* d_in, const int* in_sizes, int n_in,
                              void* d_out, int out_size)
{
    const float* inputs  = (const float*)d_in[0];
    const float* filters = (const float*)d_in[1];
    if (n_in >= 2 && in_sizes[0] == 8 * 4096 * (H_NUM * KS)) {
        filters = (const float*)d_in[0];
        inputs  = (const float*)d_in[1];
    }
    float* out = (float*)d_out;

    dim3 grid(S_LEN / TILE_S, H_NUM, 8);   // 128 x 12 x 8 = 12288 CTAs
    lightconv_kernel<<<grid, NTHREADS>>>(inputs, filters, out);
}

// round 13
// speedup vs baseline: 1.1395x; 1.0452x over previous
#include <cuda_runtime.h>

// ConvBertLightConv: dynamic depthwise conv, kernel=9, head=64.
// inputs:  [B=8, S=4096, D=768] fp32, filters: [B,S,108] fp32, out: [B,S,768].
//
// R12 (from R9 best): shrink the zero-DRAM compute tail that caps HBM duty
// cycle. Packed fma.rn.f32x2 halves FMA instruction count (144->72/thread);
// weights stored duplicated as float2{w,w} so each arrives via one broadcast
// LDS.64 (no pack ops). launch_bounds(128,7) targets 7 CTAs/SM with the full
// 12-row front-batched load burst (MLP_p1=12) kept intact. One barrier.

#define S_LEN   4096
#define D_DIM   768
#define H_NUM   12
#define HD      64
#define KS      9
#define TILE_S  32
#define SREG    4
#define NTHREADS 128                 // 8 position-groups x 16 f4-columns
#define NROWS   (SREG + KS - 1)      // 12
#define ROW_F4  (D_DIM / 4)          // 192
#define FP      12                   // padded filter row stride (float2 units)

#define FMA2(acc, w, r) \
    asm("fma.rn.f32x2 %0, %1, %2, %3;" : "=l"(acc) : "l"(w), "l"(r), "l"(acc))

__device__ __forceinline__ void stcs128(void* p, unsigned long long lo,
                                        unsigned long long hi) {
    asm volatile("st.global.cs.v2.b64 [%0], {%1,%2};\n"
                 :: "l"(p), "l"(lo), "l"(hi));
}

__global__ __launch_bounds__(NTHREADS, 7)
void lightconv_kernel(const float* __restrict__ inputs,
                      const float* __restrict__ filters,
                      float* __restrict__ out)
{
    __shared__ float2 w_s[TILE_S * FP];       // duplicated taps {w,w}, 3072 B

    const int tid = threadIdx.x;
    const int s0  = blockIdx.x * TILE_S;
    const int h   = blockIdx.y;
    const int b   = blockIdx.z;

    const int c   = tid & 15;                 // float4 column 0..15
    const int sl0 = (tid >> 4) * SREG;        // local base position

    // ---- front-batched input loads: 12 rows into registers ----
    const ulonglong2* in_g =
        (const ulonglong2*)(inputs + (size_t)b * S_LEN * D_DIM + h * HD);
    const int gbase = s0 + sl0 - (KS / 2);

    ulonglong2 rin[NROWS];
    if (s0 >= (KS / 2) && s0 + TILE_S + (KS / 2) <= S_LEN) {
        #pragma unroll
        for (int j = 0; j < NROWS; j++)
            rin[j] = __ldg(&in_g[(size_t)(gbase + j) * ROW_F4 + c]);
    } else {
        #pragma unroll
        for (int j = 0; j < NROWS; j++) {
            const int g = gbase + j;
            rin[j] = make_ulonglong2(0ull, 0ull);
            if ((unsigned)g < (unsigned)S_LEN)
                rin[j] = __ldg(&in_g[(size_t)g * ROW_F4 + c]);
        }
    }

    // ---- warp 0: load taps, softmax, publish duplicated (overlaps LDGs) ----
    if (tid < TILE_S) {
        const float* f =
            filters + (size_t)(b * S_LEN + s0 + tid) * (H_NUM * KS) + h * KS;
        float v[KS];
        float m = -1e30f;
        #pragma unroll
        for (int k = 0; k < KS; k++) {
            v[k] = __ldg(f + k);
            m = fmaxf(m, v[k]);
        }
        float sum = 0.f;
        #pragma unroll
        for (int k = 0; k < KS; k++) { v[k] = __expf(v[k] - m); sum += v[k]; }
        const float inv = 1.0f / sum;
        #pragma unroll
        for (int k = 0; k < KS; k++) {
            const float wv = v[k] * inv;
            w_s[tid * FP + k] = make_float2(wv, wv);
        }
    }
    __syncthreads();                          // the ONLY barrier

    // ---- FMA (packed f32x2): row j feeds output i at tap k = j - i ----
    unsigned long long accA[SREG], accB[SREG];
    #pragma unroll
    for (int i = 0; i < SREG; i++) { accA[i] = 0ull; accB[i] = 0ull; }

    #pragma unroll
    for (int j = 0; j < NROWS; j++) {
        const unsigned long long rA = rin[j].x;
        const unsigned long long rB = rin[j].y;
        #pragma unroll
        for (int i = 0; i < SREG; i++) {
            const int k = j - i;
            if (k >= 0 && k < KS) {
                const unsigned long long w2 =
                    *(const unsigned long long*)&w_s[(sl0 + i) * FP + k];
                FMA2(accA[i], w2, rA);
                FMA2(accB[i], w2, rB);
            }
        }
    }

    // ---- streaming stores (256B-contiguous per position) ----
    ulonglong2* out_g =
        (ulonglong2*)(out + (size_t)b * S_LEN * D_DIM + h * HD);
    #pragma unroll
    for (int i = 0; i < SREG; i++)
        stcs128(&out_g[(size_t)(s0 + sl0 + i) * ROW_F4 + c], accA[i], accB[i]);
}

extern "C" void kernel_launch(void* const* d_in, const int* in_sizes, int n_in,
                              void* d_out, int out_size)
{
    const float* inputs  = (const float*)d_in[0];
    const float* filters = (const float*)d_in[1];
    if (n_in >= 2 && in_sizes[0] == 8 * 4096 * (H_NUM * KS)) {
        filters = (const float*)d_in[0];
        inputs  = (const float*)d_in[1];
    }
    float* out = (float*)d_out;

    dim3 grid(S_LEN / TILE_S, H_NUM, 8);   // 128 x 12 x 8 = 12288 CTAs
    lightconv_kernel<<<grid, NTHREADS>>>(inputs, filters, out);
}

// round 14
// speedup vs baseline: 1.1516x; 1.0106x over previous
#include <cuda_runtime.h>

// ConvBertLightConv: dynamic depthwise conv, kernel=9, head=64.
// inputs:  [B=8, S=4096, D=768] fp32, filters: [B,S,108] fp32, out: [B,S,768].
//
// R13 (from R12): attack L1 (74.6%, now the binding unit).
//  - filters staged coalesced via 96 cp.async16 (was: 288 scattered-sector
//    LDG.32 wavefronts from warp 0) and softmaxed from smem
//  - weights read as pairs: 4x LDS.128 + 1x LDS.64 per output (20 shared ops
//    per thread instead of 36); w_s holds duplicated {w,w} float2 so each
//    64-bit lane-pair is a ready FMA2 operand
//  - unchanged: 12-row front-batched LDG burst overlapping the filter wait,
//    packed fma.rn.f32x2, streaming .cs stores, launch_bounds(128,7)

#define S_LEN   4096
#define D_DIM   768
#define H_NUM   12
#define HD      64
#define KS      9
#define TILE_S  32
#define SREG    4
#define NTHREADS 128                 // 8 position-groups x 16 f4-columns
#define NROWS   (SREG + KS - 1)      // 12
#define ROW_F4  (D_DIM / 4)          // 192
#define FPF     12                   // fraw row stride (floats)
#define FPW     12                   // w_s row stride (float2)

#define FMA2(acc, w, r) \
    asm("fma.rn.f32x2 %0, %1, %2, %3;" : "=l"(acc) : "l"(w), "l"(r), "l"(acc))

__device__ __forceinline__ void cp_async16(void* smem, const void* gmem) {
    unsigned sa = (unsigned)__cvta_generic_to_shared(smem);
    asm volatile("cp.async.ca.shared.global [%0], [%1], 16;\n"
                 :: "r"(sa), "l"(gmem));
}

__device__ __forceinline__ void stcs128(void* p, unsigned long long lo,
                                        unsigned long long hi) {
    asm volatile("st.global.cs.v2.b64 [%0], {%1,%2};\n"
                 :: "l"(p), "l"(lo), "l"(hi));
}

__global__ __launch_bounds__(NTHREADS, 7)
void lightconv_kernel(const float* __restrict__ inputs,
                      const float* __restrict__ filters,
                      float* __restrict__ out)
{
    __shared__ float fraw[TILE_S * FPF];                   // 1536 B
    __shared__ __align__(16) float2 w_s[TILE_S * FPW];     // 3072 B

    const int tid = threadIdx.x;
    const int s0  = blockIdx.x * TILE_S;
    const int h   = blockIdx.y;
    const int b   = blockIdx.z;

    const int c   = tid & 15;                 // float4 column 0..15
    const int sl0 = (tid >> 4) * SREG;        // local base position

    // ---- stage filters coalesced: 3 aligned 16B chunks per row (96 ops) ----
    const int foff  = h * KS;
    const int a0    = foff & ~3;              // aligned-down float offset
    const int shift = foff & 3;
    const float* frow0 =
        filters + (size_t)(b * S_LEN + s0) * (H_NUM * KS) + a0;

    if (tid < TILE_S * 3) {
        const int r = tid / 3;
        const int q = tid - r * 3;
        cp_async16(&fraw[r * FPF + q * 4],
                   frow0 + (size_t)r * (H_NUM * KS) + q * 4);
    }
    asm volatile("cp.async.commit_group;\n" ::: "memory");

    // ---- front-batched input loads: 12 rows into registers ----
    const ulonglong2* in_g =
        (const ulonglong2*)(inputs + (size_t)b * S_LEN * D_DIM + h * HD);
    const int gbase = s0 + sl0 - (KS / 2);

    ulonglong2 rin[NROWS];
    if (s0 >= (KS / 2) && s0 + TILE_S + (KS / 2) <= S_LEN) {
        #pragma unroll
        for (int j = 0; j < NROWS; j++)
            rin[j] = __ldg(&in_g[(size_t)(gbase + j) * ROW_F4 + c]);
    } else {
        #pragma unroll
        for (int j = 0; j < NROWS; j++) {
            const int g = gbase + j;
            rin[j] = make_ulonglong2(0ull, 0ull);
            if ((unsigned)g < (unsigned)S_LEN)
                rin[j] = __ldg(&in_g[(size_t)g * ROW_F4 + c]);
        }
    }

    // ---- filters arrive (input LDGs still in flight); softmax ----
    asm volatile("cp.async.wait_group 0;\n" ::: "memory");
    __syncthreads();

    if (tid < TILE_S) {
        float v[KS];
        float m = -1e30f;
        #pragma unroll
        for (int k = 0; k < KS; k++) {
            v[k] = fraw[tid * FPF + shift + k];
            m = fmaxf(m, v[k]);
        }
        float sum = 0.f;
        #pragma unroll
        for (int k = 0; k < KS; k++) { v[k] = __expf(v[k] - m); sum += v[k]; }
        const float inv = 1.0f / sum;
        #pragma unroll
        for (int k = 0; k < KS; k++) {
            const float wv = v[k] * inv;
            w_s[tid * FPW + k] = make_float2(wv, wv);
        }
    }
    __syncthreads();

    // ---- FMA (packed f32x2), paired weight loads ----
    unsigned long long accA[SREG], accB[SREG];
    #pragma unroll
    for (int i = 0; i < SREG; i++) { accA[i] = 0ull; accB[i] = 0ull; }

    #pragma unroll
    for (int i = 0; i < SREG; i++) {
        const float2* wrow = &w_s[(sl0 + i) * FPW];
        #pragma unroll
        for (int kp = 0; kp < 4; kp++) {      // taps 2kp, 2kp+1
            const ulonglong2 wp = *(const ulonglong2*)&wrow[2 * kp];
            FMA2(accA[i], wp.x, rin[i + 2 * kp].x);
            FMA2(accB[i], wp.x, rin[i + 2 * kp].y);
            FMA2(accA[i], wp.y, rin[i + 2 * kp + 1].x);
            FMA2(accB[i], wp.y, rin[i + 2 * kp + 1].y);
        }
        const unsigned long long w8 =
            *(const unsigned long long*)&wrow[8];  // tap 8
        FMA2(accA[i], w8, rin[i + 8].x);
        FMA2(accB[i], w8, rin[i + 8].y);
    }

    // ---- streaming stores (256B-contiguous per position) ----
    ulonglong2* out_g =
        (ulonglong2*)(out + (size_t)b * S_LEN * D_DIM + h * HD);
    #pragma unroll
    for (int i = 0; i < SREG; i++)
        stcs128(&out_g[(size_t)(s0 + sl0 + i) * ROW_F4 + c], accA[i], accB[i]);
}

extern "C" void kernel_launch(void* const* d_in, const int* in_sizes, int n_in,
                              void* d_out, int out_size)
{
    const float* inputs  = (const float*)d_in[0];
    const float* filters = (const float*)d_in[1];
    if (n_in >= 2 && in_sizes[0] == 8 * 4096 * (H_NUM * KS)) {
        filters = (const float*)d_in[0];
        inputs  = (const float*)d_in[1];
    }
    float* out = (float*)d_out;

    dim3 grid(S_LEN / TILE_S, H_NUM, 8);   // 128 x 12 x 8 = 12288 CTAs
    lightconv_kernel<<<grid, NTHREADS>>>(inputs, filters, out);
}

// round 15
// speedup vs baseline: 1.1746x; 1.0200x over previous
#include <cuda_runtime.h>

// ConvBertLightConv: dynamic depthwise conv, kernel=9, head=64.
// inputs:  [B=8, S=4096, D=768] fp32, filters: [B,S,108] fp32, out: [B,S,768].
//
// R14 (from R13): fuse compute+store per output position so only ONE
// accumulator pair is live at a time (16 -> 4 regs). Peak live set drops to
// ~60 regs -> launch_bounds(128,8): 8 CTAs/SM, 32 warps (occ ~50%) while
// keeping the full 12-row front-batched LDG burst (MLP_p1=12).
// Kept from R13: coalesced cp.async filter staging, duplicated {w,w} float2
// weights read as 4xLDS.128+1xLDS.64, packed fma.rn.f32x2, .cs stores.

#define S_LEN   4096
#define D_DIM   768
#define H_NUM   12
#define HD      64
#define KS      9
#define TILE_S  32
#define SREG    4
#define NTHREADS 128                 // 8 position-groups x 16 f4-columns
#define NROWS   (SREG + KS - 1)      // 12
#define ROW_F4  (D_DIM / 4)          // 192
#define FPF     12                   // fraw row stride (floats)
#define FPW     12                   // w_s row stride (float2)

#define FMA2(acc, w, r) \
    asm("fma.rn.f32x2 %0, %1, %2, %3;" : "=l"(acc) : "l"(w), "l"(r), "l"(acc))

__device__ __forceinline__ void cp_async16(void* smem, const void* gmem) {
    unsigned sa = (unsigned)__cvta_generic_to_shared(smem);
    asm volatile("cp.async.ca.shared.global [%0], [%1], 16;\n"
                 :: "r"(sa), "l"(gmem));
}

__device__ __forceinline__ void stcs128(void* p, unsigned long long lo,
                                        unsigned long long hi) {
    asm volatile("st.global.cs.v2.b64 [%0], {%1,%2};\n"
                 :: "l"(p), "l"(lo), "l"(hi));
}

__global__ __launch_bounds__(NTHREADS, 8)
void lightconv_kernel(const float* __restrict__ inputs,
                      const float* __restrict__ filters,
                      float* __restrict__ out)
{
    __shared__ float fraw[TILE_S * FPF];                   // 1536 B
    __shared__ __align__(16) float2 w_s[TILE_S * FPW];     // 3072 B

    const int tid = threadIdx.x;
    const int s0  = blockIdx.x * TILE_S;
    const int h   = blockIdx.y;
    const int b   = blockIdx.z;

    const int c   = tid & 15;                 // float4 column 0..15
    const int sl0 = (tid >> 4) * SREG;        // local base position

    // ---- stage filters coalesced: 3 aligned 16B chunks per row (96 ops) ----
    const int foff  = h * KS;
    const int a0    = foff & ~3;              // aligned-down float offset
    const int shift = foff & 3;
    const float* frow0 =
        filters + (size_t)(b * S_LEN + s0) * (H_NUM * KS) + a0;

    if (tid < TILE_S * 3) {
        const int r = tid / 3;
        const int q = tid - r * 3;
        cp_async16(&fraw[r * FPF + q * 4],
                   frow0 + (size_t)r * (H_NUM * KS) + q * 4);
    }
    asm volatile("cp.async.commit_group;\n" ::: "memory");

    // ---- front-batched input loads: 12 rows into registers ----
    const ulonglong2* in_g =
        (const ulonglong2*)(inputs + (size_t)b * S_LEN * D_DIM + h * HD);
    const int gbase = s0 + sl0 - (KS / 2);

    ulonglong2 rin[NROWS];
    if (s0 >= (KS / 2) && s0 + TILE_S + (KS / 2) <= S_LEN) {
        #pragma unroll
        for (int j = 0; j < NROWS; j++)
            rin[j] = __ldg(&in_g[(size_t)(gbase + j) * ROW_F4 + c]);
    } else {
        #pragma unroll
        for (int j = 0; j < NROWS; j++) {
            const int g = gbase + j;
            rin[j] = make_ulonglong2(0ull, 0ull);
            if ((unsigned)g < (unsigned)S_LEN)
                rin[j] = __ldg(&in_g[(size_t)g * ROW_F4 + c]);
        }
    }

    // ---- filters arrive (input LDGs still in flight); softmax ----
    asm volatile("cp.async.wait_group 0;\n" ::: "memory");
    __syncthreads();

    if (tid < TILE_S) {
        float v[KS];
        float m = -1e30f;
        #pragma unroll
        for (int k = 0; k < KS; k++) {
            v[k] = fraw[tid * FPF + shift + k];
            m = fmaxf(m, v[k]);
        }
        float sum = 0.f;
        #pragma unroll
        for (int k = 0; k < KS; k++) { v[k] = __expf(v[k] - m); sum += v[k]; }
        const float inv = 1.0f / sum;
        #pragma unroll
        for (int k = 0; k < KS; k++) {
            const float wv = v[k] * inv;
            w_s[tid * FPW + k] = make_float2(wv, wv);
        }
    }
    __syncthreads();

    // ---- fused FMA + store per output: one live accumulator pair ----
    ulonglong2* out_g =
        (ulonglong2*)(out + (size_t)b * S_LEN * D_DIM + h * HD);

    #pragma unroll
    for (int i = 0; i < SREG; i++) {
        const float2* wrow = &w_s[(sl0 + i) * FPW];
        unsigned long long accA = 0ull, accB = 0ull;
        #pragma unroll
        for (int kp = 0; kp < 4; kp++) {      // taps 2kp, 2kp+1
            const ulonglong2 wp = *(const ulonglong2*)&wrow[2 * kp];
            FMA2(accA, wp.x, rin[i + 2 * kp].x);
            FMA2(accB, wp.x, rin[i + 2 * kp].y);
            FMA2(accA, wp.y, rin[i + 2 * kp + 1].x);
            FMA2(accB, wp.y, rin[i + 2 * kp + 1].y);
        }
        const unsigned long long w8 =
            *(const unsigned long long*)&wrow[8];  // tap 8
        FMA2(accA, w8, rin[i + 8].x);
        FMA2(accB, w8, rin[i + 8].y);

        stcs128(&out_g[(size_t)(s0 + sl0 + i) * ROW_F4 + c], accA, accB);
    }
}

extern "C" void kernel_launch(void* const* d_in, const int* in_sizes, int n_in,
                              void* d_out, int out_size)
{
    const float* inputs  = (const float*)d_in[0];
    const float* filters = (const float*)d_in[1];
    if (n_in >= 2 && in_sizes[0] == 8 * 4096 * (H_NUM * KS)) {
        filters = (const float*)d_in[0];
        inputs  = (const float*)d_in[1];
    }
    float* out = (float*)d_out;

    dim3 grid(S_LEN / TILE_S, H_NUM, 8);   // 128 x 12 x 8 = 12288 CTAs
    lightconv_kernel<<<grid, NTHREADS>>>(inputs, filters, out);
}

// round 16
// speedup vs baseline: 1.2098x; 1.0300x over previous
#include <cuda_runtime.h>

// ConvBertLightConv: dynamic depthwise conv, kernel=9, head=64.
// inputs:  [B=8, S=4096, D=768] fp32, filters: [B,S,108] fp32, out: [B,S,768].
//
// R15 (from R14): L1 is the saturated unit (75.7%) -> cut LDS bytes.
// Weights stored UN-duplicated (plain float, stride 12); per output read
// 2x LDS.128 + 1x LDS.32 (36B) instead of 5 duplicated loads (72B), and
// build each {w,w} fma.rn.f32x2 operand with one mov.b64 on the idle ALU
// pipe. LDS insts/CTA drop 80 -> 48 (~-22% L1 cycles).
// Kept: 12-row front-batched LDG burst (MLP_p1=12) overlapping cp.async
// filter staging, fused per-output store, .cs stores, launch_bounds(128,8).

#define S_LEN   4096
#define D_DIM   768
#define H_NUM   12
#define HD      64
#define KS      9
#define TILE_S  32
#define SREG    4
#define NTHREADS 128                 // 8 position-groups x 16 f4-columns
#define NROWS   (SREG + KS - 1)      // 12
#define ROW_F4  (D_DIM / 4)          // 192
#define FPF     12                   // fraw row stride (floats)
#define FPW     12                   // w_s row stride (floats, 48B rows)

#define FMA2(acc, w, r) \
    asm("fma.rn.f32x2 %0, %1, %2, %3;" : "=l"(acc) : "l"(w), "l"(r), "l"(acc))

#define PACK2(dst, w) \
    asm("mov.b64 %0, {%1, %1};" : "=l"(dst) : "f"(w))

__device__ __forceinline__ void cp_async16(void* smem, const void* gmem) {
    unsigned sa = (unsigned)__cvta_generic_to_shared(smem);
    asm volatile("cp.async.ca.shared.global [%0], [%1], 16;\n"
                 :: "r"(sa), "l"(gmem));
}

__device__ __forceinline__ void stcs128(void* p, unsigned long long lo,
                                        unsigned long long hi) {
    asm volatile("st.global.cs.v2.b64 [%0], {%1,%2};\n"
                 :: "l"(p), "l"(lo), "l"(hi));
}

__global__ __launch_bounds__(NTHREADS, 8)
void lightconv_kernel(const float* __restrict__ inputs,
                      const float* __restrict__ filters,
                      float* __restrict__ out)
{
    __shared__ float fraw[TILE_S * FPF];                   // 1536 B
    __shared__ __align__(16) float w_s[TILE_S * FPW];      // 1536 B

    const int tid = threadIdx.x;
    const int s0  = blockIdx.x * TILE_S;
    const int h   = blockIdx.y;
    const int b   = blockIdx.z;

    const int c   = tid & 15;                 // float4 column 0..15
    const int sl0 = (tid >> 4) * SREG;        // local base position

    // ---- stage filters coalesced: 3 aligned 16B chunks per row (96 ops) ----
    const int foff  = h * KS;
    const int a0    = foff & ~3;              // aligned-down float offset
    const int shift = foff & 3;
    const float* frow0 =
        filters + (size_t)(b * S_LEN + s0) * (H_NUM * KS) + a0;

    if (tid < TILE_S * 3) {
        const int r = tid / 3;
        const int q = tid - r * 3;
        cp_async16(&fraw[r * FPF + q * 4],
                   frow0 + (size_t)r * (H_NUM * KS) + q * 4);
    }
    asm volatile("cp.async.commit_group;\n" ::: "memory");

    // ---- front-batched input loads: 12 rows into registers ----
    const ulonglong2* in_g =
        (const ulonglong2*)(inputs + (size_t)b * S_LEN * D_DIM + h * HD);
    const int gbase = s0 + sl0 - (KS / 2);

    ulonglong2 rin[NROWS];
    if (s0 >= (KS / 2) && s0 + TILE_S + (KS / 2) <= S_LEN) {
        #pragma unroll
        for (int j = 0; j < NROWS; j++)
            rin[j] = __ldg(&in_g[(size_t)(gbase + j) * ROW_F4 + c]);
    } else {
        #pragma unroll
        for (int j = 0; j < NROWS; j++) {
            const int g = gbase + j;
            rin[j] = make_ulonglong2(0ull, 0ull);
            if ((unsigned)g < (unsigned)S_LEN)
                rin[j] = __ldg(&in_g[(size_t)g * ROW_F4 + c]);
        }
    }

    // ---- filters arrive (input LDGs still in flight); softmax ----
    asm volatile("cp.async.wait_group 0;\n" ::: "memory");
    __syncthreads();

    if (tid < TILE_S) {
        float v[KS];
        float m = -1e30f;
        #pragma unroll
        for (int k = 0; k < KS; k++) {
            v[k] = fraw[tid * FPF + shift + k];
            m = fmaxf(m, v[k]);
        }
        float sum = 0.f;
        #pragma unroll
        for (int k = 0; k < KS; k++) { v[k] = __expf(v[k] - m); sum += v[k]; }
        const float inv = 1.0f / sum;
        #pragma unroll
        for (int k = 0; k < KS; k++)
            w_s[tid * FPW + k] = v[k] * inv;
    }
    __syncthreads();

    // ---- fused FMA + store per output; weights via 3 LDS + ALU pack ----
    ulonglong2* out_g =
        (ulonglong2*)(out + (size_t)b * S_LEN * D_DIM + h * HD);

    #pragma unroll
    for (int i = 0; i < SREG; i++) {
        const float* wrow = &w_s[(sl0 + i) * FPW];   // 48B-aligned row
        const float4 wa = *(const float4*)(wrow);     // taps 0..3
        const float4 wb = *(const float4*)(wrow + 4); // taps 4..7
        const float  wc = wrow[8];                    // tap 8
        const float wv[KS] = {wa.x, wa.y, wa.z, wa.w,
                              wb.x, wb.y, wb.z, wb.w, wc};

        unsigned long long accA = 0ull, accB = 0ull;
        #pragma unroll
        for (int k = 0; k < KS; k++) {
            unsigned long long w2;
            PACK2(w2, wv[k]);
            FMA2(accA, w2, rin[i + k].x);
            FMA2(accB, w2, rin[i + k].y);
        }

        stcs128(&out_g[(size_t)(s0 + sl0 + i) * ROW_F4 + c], accA, accB);
    }
}

extern "C" void kernel_launch(void* const* d_in, const int* in_sizes, int n_in,
                              void* d_out, int out_size)
{
    const float* inputs  = (const float*)d_in[0];
    const float* filters = (const float*)d_in[1];
    if (n_in >= 2 && in_sizes[0] == 8 * 4096 * (H_NUM * KS)) {
        filters = (const float*)d_in[0];
        inputs  = (const float*)d_in[1];
    }
    float* out = (float*)d_out;

    dim3 grid(S_LEN / TILE_S, H_NUM, 8);   // 128 x 12 x 8 = 12288 CTAs
    lightconv_kernel<<<grid, NTHREADS>>>(inputs, filters, out);
}

// round 17
// speedup vs baseline: 1.2108x; 1.0009x over previous
#include <cuda_runtime.h>

// ConvBertLightConv: dynamic depthwise conv, kernel=9, head=64.
// inputs:  [B=8, S=4096, D=768] fp32, filters: [B,S,108] fp32, out: [B,S,768].
//
// R16 (from R15): cut input-LDG amplification 3x -> 2x. SREG=8 (TILE_S=64):
// each thread makes 8 outputs from 16 rows via a 10-row rolling register
// window: front-batch rows 0..9 (MLP_p1=10), then after each fused
// compute+store of output i, prefetch row i+10 into the freed slot
// (prefetch distance ~2 output blocks, unlike R11's too-tight window).
// Kept: un-duplicated weights (2xLDS.128+1xLDS.32 + mov.b64 pack on ALU),
// packed fma.rn.f32x2, coalesced cp.async filter staging, .cs stores.

#define S_LEN   4096
#define D_DIM   768
#define H_NUM   12
#define HD      64
#define KS      9
#define TILE_S  64
#define SREG    8
#define NTHREADS 128                 // 8 position-groups x 16 f4-columns
#define WIN     10                   // rolling row window
#define NROWS   (SREG + KS - 1)      // 16
#define ROW_F4  (D_DIM / 4)          // 192
#define FPF     12                   // fraw row stride (floats)
#define FPW     12                   // w_s row stride (floats, 48B rows)

#define FMA2(acc, w, r) \
    asm("fma.rn.f32x2 %0, %1, %2, %3;" : "=l"(acc) : "l"(w), "l"(r), "l"(acc))

#define PACK2(dst, w) \
    asm("mov.b64 %0, {%1, %1};" : "=l"(dst) : "f"(w))

__device__ __forceinline__ void cp_async16(void* smem, const void* gmem) {
    unsigned sa = (unsigned)__cvta_generic_to_shared(smem);
    asm volatile("cp.async.ca.shared.global [%0], [%1], 16;\n"
                 :: "r"(sa), "l"(gmem));
}

__device__ __forceinline__ void stcs128(void* p, unsigned long long lo,
                                        unsigned long long hi) {
    asm volatile("st.global.cs.v2.b64 [%0], {%1,%2};\n"
                 :: "l"(p), "l"(lo), "l"(hi));
}

template <bool EDGE>
__device__ __forceinline__ void conv_body(const ulonglong2* __restrict__ in_g,
                                          const float* __restrict__ w_s,
                                          ulonglong2* __restrict__ out_g,
                                          int s0, int sl0, int c)
{
    const int gbase = s0 + sl0 - (KS / 2);

    // front-batch rows 0..9 (MLP_p1 = 10)
    ulonglong2 rin[WIN];
    #pragma unroll
    for (int j = 0; j < WIN; j++) {
        if (EDGE) {
            const int g = gbase + j;
            rin[j] = make_ulonglong2(0ull, 0ull);
            if ((unsigned)g < (unsigned)S_LEN)
                rin[j] = __ldg(&in_g[(size_t)g * ROW_F4 + c]);
        } else {
            rin[j] = __ldg(&in_g[(size_t)(gbase + j) * ROW_F4 + c]);
        }
    }

    #pragma unroll
    for (int i = 0; i < SREG; i++) {
        const float* wrow = &w_s[(sl0 + i) * FPW];     // 48B-aligned row
        const float4 wa = *(const float4*)(wrow);      // taps 0..3
        const float4 wb = *(const float4*)(wrow + 4);  // taps 4..7
        const float  wc = wrow[8];                     // tap 8
        const float wv[KS] = {wa.x, wa.y, wa.z, wa.w,
                              wb.x, wb.y, wb.z, wb.w, wc};

        unsigned long long accA = 0ull, accB = 0ull;
        #pragma unroll
        for (int k = 0; k < KS; k++) {
            unsigned long long w2;
            PACK2(w2, wv[k]);
            FMA2(accA, w2, rin[(i + k) % WIN].x);
            FMA2(accB, w2, rin[(i + k) % WIN].y);
        }
        stcs128(&out_g[(size_t)(s0 + sl0 + i) * ROW_F4 + c], accA, accB);

        // prefetch row i+10 into the slot row i just freed
        if (i + WIN < NROWS) {
            if (EDGE) {
                const int g = gbase + i + WIN;
                rin[i % WIN] = make_ulonglong2(0ull, 0ull);
                if ((unsigned)g < (unsigned)S_LEN)
                    rin[i % WIN] = __ldg(&in_g[(size_t)g * ROW_F4 + c]);
            } else {
                rin[i % WIN] =
                    __ldg(&in_g[(size_t)(gbase + i + WIN) * ROW_F4 + c]);
            }
        }
    }
}

__global__ __launch_bounds__(NTHREADS, 8)
void lightconv_kernel(const float* __restrict__ inputs,
                      const float* __restrict__ filters,
                      float* __restrict__ out)
{
    __shared__ float fraw[TILE_S * FPF];                   // 3072 B
    __shared__ __align__(16) float w_s[TILE_S * FPW];      // 3072 B

    const int tid = threadIdx.x;
    const int s0  = blockIdx.x * TILE_S;
    const int h   = blockIdx.y;
    const int b   = blockIdx.z;

    const int c   = tid & 15;                 // float4 column 0..15
    const int sl0 = (tid >> 4) * SREG;        // local base position

    // ---- stage filters coalesced: 3 aligned 16B chunks per row (192 ops) ---
    const int foff  = h * KS;
    const int a0    = foff & ~3;              // aligned-down float offset
    const int shift = foff & 3;
    const float* frow0 =
        filters + (size_t)(b * S_LEN + s0) * (H_NUM * KS) + a0;

    #pragma unroll
    for (int idx = tid; idx < TILE_S * 3; idx += NTHREADS) {
        const int r = idx / 3;
        const int q = idx - r * 3;
        cp_async16(&fraw[r * FPF + q * 4],
                   frow0 + (size_t)r * (H_NUM * KS) + q * 4);
    }
    asm volatile("cp.async.commit_group;\n" ::: "memory");
    asm volatile("cp.async.wait_group 0;\n" ::: "memory");
    __syncthreads();

    // ---- softmax (2 warps) ----
    if (tid < TILE_S) {
        float v[KS];
        float m = -1e30f;
        #pragma unroll
        for (int k = 0; k < KS; k++) {
            v[k] = fraw[tid * FPF + shift + k];
            m = fmaxf(m, v[k]);
        }
        float sum = 0.f;
        #pragma unroll
        for (int k = 0; k < KS; k++) { v[k] = __expf(v[k] - m); sum += v[k]; }
        const float inv = 1.0f / sum;
        #pragma unroll
        for (int k = 0; k < KS; k++)
            w_s[tid * FPW + k] = v[k] * inv;
    }
    __syncthreads();

    const ulonglong2* in_g =
        (const ulonglong2*)(inputs + (size_t)b * S_LEN * D_DIM + h * HD);
    ulonglong2* out_g =
        (ulonglong2*)(out + (size_t)b * S_LEN * D_DIM + h * HD);

    if (s0 >= (KS / 2) && s0 + TILE_S + (KS / 2) <= S_LEN)
        conv_body<false>(in_g, w_s, out_g, s0, sl0, c);
    else
        conv_body<true >(in_g, w_s, out_g, s0, sl0, c);
}

extern "C" void kernel_launch(void* const* d_in, const int* in_sizes, int n_in,
                              void* d_out, int out_size)
{
    const float* inputs  = (const float*)d_in[0];
    const float* filters = (const float*)d_in[1];
    if (n_in >= 2 && in_sizes[0] == 8 * 4096 * (H_NUM * KS)) {
        filters = (const float*)d_in[0];
        inputs  = (const float*)d_in[1];
    }
    float* out = (float*)d_out;

    dim3 grid(S_LEN / TILE_S, H_NUM, 8);   // 64 x 12 x 8 = 6144 CTAs
    lightconv_kernel<<<grid, NTHREADS>>>(inputs, filters, out);
}